// round 12
// baseline (speedup 1.0000x reference)
#include <cuda_runtime.h>

#define B_  128
#define T_  512
#define H_  512
#define L_  256
#define HB_ (B_ * H_)

__device__ float    g_ig[(size_t)T_ * B_ * 3 * H_];
__device__ unsigned g_h[2 * HB_];        // step-parity double buffer (tf32 words)
__device__ float    g_hx[HB_];           // exact fp32 h_final
__device__ unsigned long long g_flag[128 * 16];

__device__ __forceinline__ unsigned f2tf(float f) {
    unsigned u;
    asm("cvt.rna.tf32.f32 %0, %1;" : "=r"(u) : "f"(f));
    return u;
}
__device__ __forceinline__ void mma8(float c[4],
                                     unsigned a0, unsigned a1, unsigned a2, unsigned a3,
                                     unsigned b0, unsigned b1) {
    asm volatile(
        "mma.sync.aligned.m16n8k8.row.col.f32.tf32.tf32.f32 "
        "{%0,%1,%2,%3}, {%4,%5,%6,%7}, {%8,%9}, {%0,%1,%2,%3};"
        : "+f"(c[0]), "+f"(c[1]), "+f"(c[2]), "+f"(c[3])
        : "r"(a0), "r"(a1), "r"(a2), "r"(a3), "r"(b0), "r"(b1));
}
__device__ __forceinline__ float sigf(float x) { return 1.0f / (1.0f + __expf(-x)); }
__device__ __forceinline__ void red_release(unsigned long long* p) {
    asm volatile("red.add.release.gpu.global.u64 [%0], 1;" :: "l"(p) : "memory");
}
__device__ __forceinline__ unsigned long long ld_acquire(const unsigned long long* p) {
    unsigned long long v;
    asm volatile("ld.acquire.gpu.u64 %0, [%1];" : "=l"(v) : "l"(p) : "memory");
    return v;
}

__global__ void k_zero() {
    for (int i = threadIdx.x; i < 128 * 16; i += 256) g_flag[i] = 0ULL;
}

// ===========================================================================
// Kernel 1: IG = X@Wih^T + b  (FROZEN round-5 config: 857us known-good)
// ===========================================================================
__global__ void __launch_bounds__(256) k_igemm(const float* __restrict__ x,
                                               const float* __restrict__ Wih,
                                               const float* __restrict__ bias) {
    __shared__ unsigned As[128][20];
    __shared__ unsigned Bs[128][20];

    const int t   = blockIdx.y;
    const int n0  = blockIdx.x * 128;
    const int tid = threadIdx.x;
    const int w    = tid >> 5;
    const int lane = tid & 31;
    const int gid  = lane >> 2;
    const int tig  = lane & 3;
    const int mrow = (w >> 2) * 64;
    const int ncol = (w & 3) * 32;

    float acc[4][4][4];
    #pragma unroll
    for (int i = 0; i < 4; i++)
        #pragma unroll
        for (int j = 0; j < 4; j++)
            #pragma unroll
            for (int q = 0; q < 4; q++) acc[i][j][q] = 0.0f;

    for (int k0 = 0; k0 < 512; k0 += 16) {
        #pragma unroll
        for (int it = 0; it < 2; it++) {
            int i  = tid + it * 256;
            int r  = i >> 2;
            int c4 = (i & 3) * 4;
            float4 v = *(const float4*)(x + ((size_t)r * 512 + t) * 512 + k0 + c4);
            As[r][c4 + 0] = f2tf(v.x);
            As[r][c4 + 1] = f2tf(v.y);
            As[r][c4 + 2] = f2tf(v.z);
            As[r][c4 + 3] = f2tf(v.w);
        }
        #pragma unroll
        for (int it = 0; it < 2; it++) {
            int i  = tid + it * 256;
            int r  = i >> 2;
            int c4 = (i & 3) * 4;
            float4 v = *(const float4*)(Wih + (size_t)(n0 + r) * 512 + k0 + c4);
            Bs[r][c4 + 0] = f2tf(v.x);
            Bs[r][c4 + 1] = f2tf(v.y);
            Bs[r][c4 + 2] = f2tf(v.z);
            Bs[r][c4 + 3] = f2tf(v.w);
        }
        __syncthreads();

        #pragma unroll
        for (int ks = 0; ks < 2; ks++) {
            const int kb = ks * 8;
            unsigned a[4][4];
            #pragma unroll
            for (int mt = 0; mt < 4; mt++) {
                int r = mrow + mt * 16 + gid;
                a[mt][0] = As[r][kb + tig];
                a[mt][1] = As[r + 8][kb + tig];
                a[mt][2] = As[r][kb + tig + 4];
                a[mt][3] = As[r + 8][kb + tig + 4];
            }
            #pragma unroll
            for (int nt = 0; nt < 4; nt++) {
                int n = ncol + nt * 8 + gid;
                unsigned b0 = Bs[n][kb + tig];
                unsigned b1 = Bs[n][kb + tig + 4];
                #pragma unroll
                for (int mt = 0; mt < 4; mt++)
                    mma8(acc[mt][nt], a[mt][0], a[mt][1], a[mt][2], a[mt][3], b0, b1);
            }
        }
        __syncthreads();
    }

    #pragma unroll
    for (int mt = 0; mt < 4; mt++) {
        #pragma unroll
        for (int nt = 0; nt < 4; nt++) {
            int r0 = mrow + mt * 16 + gid;
            int c0 = n0 + ncol + nt * 8 + 2 * tig;
            float bv0 = __ldg(bias + c0);
            float bv1 = __ldg(bias + c0 + 1);
            size_t base0 = ((size_t)t * 128 + r0) * 1536 + c0;
            size_t base1 = ((size_t)t * 128 + r0 + 8) * 1536 + c0;
            *(float2*)&g_ig[base0] = make_float2(acc[mt][nt][0] + bv0, acc[mt][nt][1] + bv1);
            *(float2*)&g_ig[base1] = make_float2(acc[mt][nt][2] + bv0, acc[mt][nt][3] + bv1);
        }
    }
}

// ===========================================================================
// Kernel 2: persistent GRU recurrence — round-11 body with:
//   (a) Sg step-parity double buffer -> ONE __syncthreads per step,
//   (b) per-warp flag release (8 arrivals/step, poll target 8t).
//   grid 128 (4 row-groups x 32 col-groups), 256 thr (8 warps = K-groups).
// ===========================================================================
#define WS_PITCH 516
#define SG_PITCH 52
#define SG_WORDS (8 * 32 * SG_PITCH)
#define SMEM_K2_BYTES ((80 * WS_PITCH + SG_WORDS) * 4)   // 218368 B

__global__ void __launch_bounds__(256, 1) k_rec(const float* __restrict__ Whh,
                                                const float* __restrict__ bn) {
    extern __shared__ unsigned smem[];
    unsigned* Ws  = smem;                          // [48][516] init only
    unsigned* Hs  = smem + 48 * WS_PITCH;          // [32][516] tf32 h tile
    float*    SgA = (float*)smem;                  // aliases Ws after frag pull
    float*    SgB = (float*)(smem + 80 * WS_PITCH);

    const int tid  = threadIdx.x;
    const int lane = tid & 31;
    const int w    = tid >> 5;
    const int gid  = lane >> 2;
    const int tig  = lane & 3;
    const int mg   = blockIdx.x >> 5;
    const int cg   = blockIdx.x & 31;
    const int rowbase = mg * 32;
    const int colbase = cg * 16;

    for (int i = tid; i < 48 * 128; i += 256) {
        int lr   = i >> 7;
        int c4   = (i & 127) * 4;
        int grow = (lr >> 4) * 512 + colbase + (lr & 15);
        float4 v = *(const float4*)(Whh + (size_t)grow * 512 + c4);
        uint4 u = make_uint4(f2tf(v.x), f2tf(v.y), f2tf(v.z), f2tf(v.w));
        *(uint4*)&Ws[lr * WS_PITCH + c4] = u;
    }
    for (int i = tid; i < 32 * WS_PITCH; i += 256) Hs[i] = 0u;
    __syncthreads();

    const int kbase = w * 64;
    unsigned wf[8][6][2];
    #pragma unroll
    for (int kt = 0; kt < 8; kt++)
        #pragma unroll
        for (int nt = 0; nt < 6; nt++) {
            int base = (nt * 8 + gid) * WS_PITCH + kbase + kt * 8 + tig;
            wf[kt][nt][0] = Ws[base];
            wf[kt][nt][1] = Ws[base + 4];
        }
    __syncthreads();   // Ws free -> SgA

    const int bb = tid >> 3;
    const int jj = (tid * 2) & 15;
    const float bn0 = __ldg(bn + colbase + jj);
    const float bn1 = __ldg(bn + colbase + jj + 1);
    float2 hp = make_float2(0.0f, 0.0f);

    unsigned long long* myflag = &g_flag[(mg * 32 + cg) * 16];
    const unsigned long long* pf = &g_flag[(mg * 32 + w * 4 + (lane & 3)) * 16];
    const int rs_half = lane >> 4;
    const int rs_c4   = (lane & 15) * 4;

    for (int t = 0; t < T_; t++) {
        const float* igb = g_ig + ((size_t)t * 128 + rowbase + bb) * 1536 + colbase + jj;
        float2 igr = __ldg((const float2*)(igb));
        float2 igz = __ldg((const float2*)(igb + 512));
        float2 ign = __ldg((const float2*)(igb + 1024));

        if (t > 0) {
            // Parallel wait: lanes 0..3 poll this warp's 4 producers (8 warps each)
            if (lane < 4) {
                const unsigned long long tgt = 8ULL * (unsigned long long)t;
                while (ld_acquire(pf) < tgt) { }
            }
            __syncwarp();
            // Full restage of own K slice from parity buffer (t-1)&1
            const unsigned* hsrc = g_h + (size_t)((t - 1) & 1) * HB_;
            #pragma unroll
            for (int rr = 0; rr < 16; rr++) {
                int row = rr * 2 + rs_half;
                const uint4* src = (const uint4*)(hsrc + (rowbase + row) * 512 + kbase + rs_c4);
                uint4 v;
                asm volatile("ld.global.cg.v4.u32 {%0,%1,%2,%3}, [%4];"
                             : "=r"(v.x), "=r"(v.y), "=r"(v.z), "=r"(v.w) : "l"(src));
                *(uint4*)&Hs[row * WS_PITCH + kbase + rs_c4] = v;
            }
        }

        float c[2][6][4];
        #pragma unroll
        for (int m = 0; m < 2; m++)
            #pragma unroll
            for (int n = 0; n < 6; n++)
                #pragma unroll
                for (int q = 0; q < 4; q++) c[m][n][q] = 0.0f;

        #pragma unroll
        for (int kt = 0; kt < 8; kt++) {
            const int kb = kbase + kt * 8;
            unsigned a[2][4];
            #pragma unroll
            for (int m = 0; m < 2; m++) {
                int r = m * 16 + gid;
                a[m][0] = Hs[r * WS_PITCH + kb + tig];
                a[m][1] = Hs[(r + 8) * WS_PITCH + kb + tig];
                a[m][2] = Hs[r * WS_PITCH + kb + tig + 4];
                a[m][3] = Hs[(r + 8) * WS_PITCH + kb + tig + 4];
            }
            #pragma unroll
            for (int n = 0; n < 6; n++) {
                mma8(c[0][n], a[0][0], a[0][1], a[0][2], a[0][3], wf[kt][n][0], wf[kt][n][1]);
                mma8(c[1][n], a[1][0], a[1][1], a[1][2], a[1][3], wf[kt][n][0], wf[kt][n][1]);
            }
        }

        float* Sgt = (t & 1) ? SgB : SgA;
        float* Sgw = Sgt + w * 32 * SG_PITCH;
        #pragma unroll
        for (int m = 0; m < 2; m++) {
            int r0 = m * 16 + gid, r1 = r0 + 8;
            #pragma unroll
            for (int n = 0; n < 6; n++) {
                int cb = n * 8 + 2 * tig;
                *(float2*)&Sgw[r0 * SG_PITCH + cb] = make_float2(c[m][n][0], c[m][n][1]);
                *(float2*)&Sgw[r1 * SG_PITCH + cb] = make_float2(c[m][n][2], c[m][n][3]);
            }
        }
        __syncthreads();   // single barrier per step (barA)

        {
            float hr0 = 0.f, hr1 = 0.f, hz0 = 0.f, hz1 = 0.f, hn0 = 0.f, hn1 = 0.f;
            #pragma unroll
            for (int k = 0; k < 8; k++) {
                const float* s = Sgt + k * 32 * SG_PITCH + bb * SG_PITCH;
                float2 vr = *(const float2*)(s + jj);
                float2 vz = *(const float2*)(s + 16 + jj);
                float2 vn = *(const float2*)(s + 32 + jj);
                hr0 += vr.x; hr1 += vr.y;
                hz0 += vz.x; hz1 += vz.y;
                hn0 += vn.x; hn1 += vn.y;
            }
            float r0 = sigf(igr.x + hr0);
            float r1 = sigf(igr.y + hr1);
            float z0 = sigf(igz.x + hz0);
            float z1 = sigf(igz.y + hz1);
            float n0 = tanhf(ign.x + r0 * (hn0 + bn0));
            float n1 = tanhf(ign.y + r1 * (hn1 + bn1));
            float h0 = (1.0f - z0) * n0 + z0 * hp.x;
            float h1 = (1.0f - z1) * n1 + z1 * hp.y;
            hp = make_float2(h0, h1);

            if (t < T_ - 1) {
                uint2 uv = make_uint2(f2tf(h0), f2tf(h1));
                unsigned* dst = g_h + (size_t)(t & 1) * HB_
                                + (rowbase + bb) * 512 + colbase + jj;
                asm volatile("st.global.cg.v2.u32 [%0], {%1,%2};"
                             :: "l"(dst), "r"(uv.x), "r"(uv.y) : "memory");
                // Per-warp release: this warp's rows (w*4..w*4+3) are done.
                __syncwarp();
                if (lane == 0) red_release(myflag);   // flag reaches 8*(t+1)
            } else {
                *(float2*)(g_hx + (rowbase + bb) * 512 + colbase + jj) =
                    make_float2(h0, h1);
            }
        }
    }
}

// ===========================================================================
// Kernel 3: out = h_final @ Wlin^T + blin; warp-per-(b,32n), coalesced. FROZEN
// ===========================================================================
__global__ void __launch_bounds__(256) k_out(const float* __restrict__ Wlin,
                                             const float* __restrict__ blin,
                                             float* __restrict__ out) {
    const int wg   = blockIdx.x * 8 + (threadIdx.x >> 5);
    const int lane = threadIdx.x & 31;
    const int b    = wg >> 4;
    const int nb   = (wg & 15) * 32;

    float4 h4[4];
    #pragma unroll
    for (int q = 0; q < 4; q++)
        h4[q] = *(const float4*)(g_hx + b * 512 + q * 128 + lane * 4);

    #pragma unroll 4
    for (int i = 0; i < 32; i++) {
        int n = nb + i;
        const float* wr = Wlin + (size_t)n * 512;
        float s = 0.0f;
        #pragma unroll
        for (int q = 0; q < 4; q++) {
            float4 wv = __ldg((const float4*)(wr + q * 128 + lane * 4));
            s += h4[q].x * wv.x + h4[q].y * wv.y + h4[q].z * wv.z + h4[q].w * wv.w;
        }
        s += __shfl_xor_sync(0xFFFFFFFF, s, 16);
        s += __shfl_xor_sync(0xFFFFFFFF, s, 8);
        s += __shfl_xor_sync(0xFFFFFFFF, s, 4);
        s += __shfl_xor_sync(0xFFFFFFFF, s, 2);
        s += __shfl_xor_sync(0xFFFFFFFF, s, 1);
        if (lane == 0) {
            float v = s + __ldg(blin + n);
            if (n < L_) out[b * L_ + n] = v;
            else        out[(size_t)B_ * L_ + b * L_ + (n - L_)] = v;
        }
    }
}

// ===========================================================================
extern "C" void kernel_launch(void* const* d_in, const int* in_sizes, int n_in,
                              void* d_out, int out_size) {
    const float* x    = (const float*)d_in[0];
    const float* Wih  = (const float*)d_in[1];
    const float* Whh  = (const float*)d_in[2];
    const float* b    = (const float*)d_in[3];
    const float* bn   = (const float*)d_in[4];
    const float* Wlin = (const float*)d_in[5];
    const float* blin = (const float*)d_in[6];
    float* out = (float*)d_out;

    cudaFuncSetAttribute(k_rec, cudaFuncAttributeMaxDynamicSharedMemorySize,
                         SMEM_K2_BYTES);

    dim3 g1(12, 512);
    k_igemm<<<g1, 256>>>(x, Wih, b);
    k_zero<<<1, 256>>>();
    k_rec<<<128, 256, SMEM_K2_BYTES>>>(Whh, bn);
    k_out<<<256, 256>>>(Wlin, blin, out);
}

// round 13
// speedup vs baseline: 1.0612x; 1.0612x over previous
#include <cuda_runtime.h>

#define B_  128
#define T_  512
#define H_  512
#define L_  256
#define HB_ (B_ * H_)

__device__ float    g_ig[(size_t)T_ * B_ * 3 * H_];
__device__ unsigned g_h[2 * HB_];        // step-parity double buffer (tf32 words)
__device__ float    g_hx[HB_];           // exact fp32 h_final
__device__ unsigned long long g_flag[128 * 32];   // 256B spacing (LTS bit-7 de-pairing)

__device__ __forceinline__ unsigned f2tf(float f) {
    unsigned u;
    asm("cvt.rna.tf32.f32 %0, %1;" : "=r"(u) : "f"(f));
    return u;
}
__device__ __forceinline__ void mma8(float c[4],
                                     unsigned a0, unsigned a1, unsigned a2, unsigned a3,
                                     unsigned b0, unsigned b1) {
    asm volatile(
        "mma.sync.aligned.m16n8k8.row.col.f32.tf32.tf32.f32 "
        "{%0,%1,%2,%3}, {%4,%5,%6,%7}, {%8,%9}, {%0,%1,%2,%3};"
        : "+f"(c[0]), "+f"(c[1]), "+f"(c[2]), "+f"(c[3])
        : "r"(a0), "r"(a1), "r"(a2), "r"(a3), "r"(b0), "r"(b1));
}
__device__ __forceinline__ float sigf(float x) { return 1.0f / (1.0f + __expf(-x)); }
// tanh(x) = 1 - 2/(1 + e^{2x}); saturates correctly: x>>0 -> 1, x<<0 -> -1.
__device__ __forceinline__ float tanhf_fast(float x) {
    return 1.0f - __fdividef(2.0f, 1.0f + __expf(2.0f * x));
}
__device__ __forceinline__ unsigned long long arrive_release(unsigned long long* p) {
    unsigned long long old;
    asm volatile("atom.add.release.gpu.u64 %0, [%1], 1;" : "=l"(old) : "l"(p) : "memory");
    return old;
}
__device__ __forceinline__ unsigned long long ld_acquire(const unsigned long long* p) {
    unsigned long long v;
    asm volatile("ld.acquire.gpu.u64 %0, [%1];" : "=l"(v) : "l"(p) : "memory");
    return v;
}

__global__ void k_zero() {
    for (int i = threadIdx.x; i < 128 * 32; i += 256) g_flag[i] = 0ULL;
}

// ===========================================================================
// Kernel 1: IG = X@Wih^T + b  (FROZEN round-5 config: 857us known-good)
// ===========================================================================
__global__ void __launch_bounds__(256) k_igemm(const float* __restrict__ x,
                                               const float* __restrict__ Wih,
                                               const float* __restrict__ bias) {
    __shared__ unsigned As[128][20];
    __shared__ unsigned Bs[128][20];

    const int t   = blockIdx.y;
    const int n0  = blockIdx.x * 128;
    const int tid = threadIdx.x;
    const int w    = tid >> 5;
    const int lane = tid & 31;
    const int gid  = lane >> 2;
    const int tig  = lane & 3;
    const int mrow = (w >> 2) * 64;
    const int ncol = (w & 3) * 32;

    float acc[4][4][4];
    #pragma unroll
    for (int i = 0; i < 4; i++)
        #pragma unroll
        for (int j = 0; j < 4; j++)
            #pragma unroll
            for (int q = 0; q < 4; q++) acc[i][j][q] = 0.0f;

    for (int k0 = 0; k0 < 512; k0 += 16) {
        #pragma unroll
        for (int it = 0; it < 2; it++) {
            int i  = tid + it * 256;
            int r  = i >> 2;
            int c4 = (i & 3) * 4;
            float4 v = *(const float4*)(x + ((size_t)r * 512 + t) * 512 + k0 + c4);
            As[r][c4 + 0] = f2tf(v.x);
            As[r][c4 + 1] = f2tf(v.y);
            As[r][c4 + 2] = f2tf(v.z);
            As[r][c4 + 3] = f2tf(v.w);
        }
        #pragma unroll
        for (int it = 0; it < 2; it++) {
            int i  = tid + it * 256;
            int r  = i >> 2;
            int c4 = (i & 3) * 4;
            float4 v = *(const float4*)(Wih + (size_t)(n0 + r) * 512 + k0 + c4);
            Bs[r][c4 + 0] = f2tf(v.x);
            Bs[r][c4 + 1] = f2tf(v.y);
            Bs[r][c4 + 2] = f2tf(v.z);
            Bs[r][c4 + 3] = f2tf(v.w);
        }
        __syncthreads();

        #pragma unroll
        for (int ks = 0; ks < 2; ks++) {
            const int kb = ks * 8;
            unsigned a[4][4];
            #pragma unroll
            for (int mt = 0; mt < 4; mt++) {
                int r = mrow + mt * 16 + gid;
                a[mt][0] = As[r][kb + tig];
                a[mt][1] = As[r + 8][kb + tig];
                a[mt][2] = As[r][kb + tig + 4];
                a[mt][3] = As[r + 8][kb + tig + 4];
            }
            #pragma unroll
            for (int nt = 0; nt < 4; nt++) {
                int n = ncol + nt * 8 + gid;
                unsigned b0 = Bs[n][kb + tig];
                unsigned b1 = Bs[n][kb + tig + 4];
                #pragma unroll
                for (int mt = 0; mt < 4; mt++)
                    mma8(acc[mt][nt], a[mt][0], a[mt][1], a[mt][2], a[mt][3], b0, b1);
            }
        }
        __syncthreads();
    }

    #pragma unroll
    for (int mt = 0; mt < 4; mt++) {
        #pragma unroll
        for (int nt = 0; nt < 4; nt++) {
            int r0 = mrow + mt * 16 + gid;
            int c0 = n0 + ncol + nt * 8 + 2 * tig;
            float bv0 = __ldg(bias + c0);
            float bv1 = __ldg(bias + c0 + 1);
            size_t base0 = ((size_t)t * 128 + r0) * 1536 + c0;
            size_t base1 = ((size_t)t * 128 + r0 + 8) * 1536 + c0;
            *(float2*)&g_ig[base0] = make_float2(acc[mt][nt][0] + bv0, acc[mt][nt][1] + bv1);
            *(float2*)&g_ig[base1] = make_float2(acc[mt][nt][2] + bv0, acc[mt][nt][3] + bv1);
        }
    }
}

// ===========================================================================
// Kernel 2: persistent GRU recurrence — EXACT round-11 structure
//   (2 barriers/step, tid0 release, parity g_h) + 256B flag spacing
//   + fast tanh in the epilogue.
// ===========================================================================
#define WS_PITCH 516
#define SG_PITCH 52
#define SMEM_K2_BYTES (80 * WS_PITCH * 4)   // Ws+Hs; Sg aliases Ws

__global__ void __launch_bounds__(256, 1) k_rec(const float* __restrict__ Whh,
                                                const float* __restrict__ bn) {
    extern __shared__ unsigned smem[];
    unsigned* Ws = smem;                     // [48][516] init only
    unsigned* Hs = smem + 48 * WS_PITCH;     // [32][516] tf32 h tile
    float*    Sg = (float*)smem;             // [8][32][52] (aliases Ws)

    const int tid  = threadIdx.x;
    const int lane = tid & 31;
    const int w    = tid >> 5;
    const int gid  = lane >> 2;
    const int tig  = lane & 3;
    const int mg   = blockIdx.x >> 5;
    const int cg   = blockIdx.x & 31;
    const int rowbase = mg * 32;
    const int colbase = cg * 16;

    for (int i = tid; i < 48 * 128; i += 256) {
        int lr   = i >> 7;
        int c4   = (i & 127) * 4;
        int grow = (lr >> 4) * 512 + colbase + (lr & 15);
        float4 v = *(const float4*)(Whh + (size_t)grow * 512 + c4);
        uint4 u = make_uint4(f2tf(v.x), f2tf(v.y), f2tf(v.z), f2tf(v.w));
        *(uint4*)&Ws[lr * WS_PITCH + c4] = u;
    }
    for (int i = tid; i < 32 * WS_PITCH; i += 256) Hs[i] = 0u;
    __syncthreads();

    const int kbase = w * 64;
    unsigned wf[8][6][2];
    #pragma unroll
    for (int kt = 0; kt < 8; kt++)
        #pragma unroll
        for (int nt = 0; nt < 6; nt++) {
            int base = (nt * 8 + gid) * WS_PITCH + kbase + kt * 8 + tig;
            wf[kt][nt][0] = Ws[base];
            wf[kt][nt][1] = Ws[base + 4];
        }
    __syncthreads();   // Ws free -> Sg

    const int bb = tid >> 3;
    const int jj = (tid * 2) & 15;
    const float bn0 = __ldg(bn + colbase + jj);
    const float bn1 = __ldg(bn + colbase + jj + 1);
    float2 hp = make_float2(0.0f, 0.0f);

    float* Sgw = Sg + w * 32 * SG_PITCH;
    unsigned long long* myflag = &g_flag[(mg * 32 + cg) * 32];
    const unsigned long long* pf = &g_flag[(mg * 32 + w * 4 + (lane & 3)) * 32];
    const int rs_half = lane >> 4;
    const int rs_c4   = (lane & 15) * 4;

    for (int t = 0; t < T_; t++) {
        const float* igb = g_ig + ((size_t)t * 128 + rowbase + bb) * 1536 + colbase + jj;
        float2 igr = __ldg((const float2*)(igb));
        float2 igz = __ldg((const float2*)(igb + 512));
        float2 ign = __ldg((const float2*)(igb + 1024));

        if (t > 0) {
            // Parallel wait: lanes 0..3 each poll one of this warp's 4 producers
            if (lane < 4) {
                while (ld_acquire(pf) < (unsigned long long)t) { }
            }
            __syncwarp();
            // Full restage of own K slice from parity buffer (t-1)&1
            const unsigned* hsrc = g_h + (size_t)((t - 1) & 1) * HB_;
            #pragma unroll
            for (int rr = 0; rr < 16; rr++) {
                int row = rr * 2 + rs_half;
                const uint4* src = (const uint4*)(hsrc + (rowbase + row) * 512 + kbase + rs_c4);
                uint4 v;
                asm volatile("ld.global.cg.v4.u32 {%0,%1,%2,%3}, [%4];"
                             : "=r"(v.x), "=r"(v.y), "=r"(v.z), "=r"(v.w) : "l"(src));
                *(uint4*)&Hs[row * WS_PITCH + kbase + rs_c4] = v;
            }
        }

        float c[2][6][4];
        #pragma unroll
        for (int m = 0; m < 2; m++)
            #pragma unroll
            for (int n = 0; n < 6; n++)
                #pragma unroll
                for (int q = 0; q < 4; q++) c[m][n][q] = 0.0f;

        #pragma unroll
        for (int kt = 0; kt < 8; kt++) {
            const int kb = kbase + kt * 8;
            unsigned a[2][4];
            #pragma unroll
            for (int m = 0; m < 2; m++) {
                int r = m * 16 + gid;
                a[m][0] = Hs[r * WS_PITCH + kb + tig];
                a[m][1] = Hs[(r + 8) * WS_PITCH + kb + tig];
                a[m][2] = Hs[r * WS_PITCH + kb + tig + 4];
                a[m][3] = Hs[(r + 8) * WS_PITCH + kb + tig + 4];
            }
            #pragma unroll
            for (int n = 0; n < 6; n++) {
                mma8(c[0][n], a[0][0], a[0][1], a[0][2], a[0][3], wf[kt][n][0], wf[kt][n][1]);
                mma8(c[1][n], a[1][0], a[1][1], a[1][2], a[1][3], wf[kt][n][0], wf[kt][n][1]);
            }
        }

        #pragma unroll
        for (int m = 0; m < 2; m++) {
            int r0 = m * 16 + gid, r1 = r0 + 8;
            #pragma unroll
            for (int n = 0; n < 6; n++) {
                int cb = n * 8 + 2 * tig;
                *(float2*)&Sgw[r0 * SG_PITCH + cb] = make_float2(c[m][n][0], c[m][n][1]);
                *(float2*)&Sgw[r1 * SG_PITCH + cb] = make_float2(c[m][n][2], c[m][n][3]);
            }
        }
        __syncthreads();

        {
            float hr0 = 0.f, hr1 = 0.f, hz0 = 0.f, hz1 = 0.f, hn0 = 0.f, hn1 = 0.f;
            #pragma unroll
            for (int k = 0; k < 8; k++) {
                const float* s = Sg + k * 32 * SG_PITCH + bb * SG_PITCH;
                float2 vr = *(const float2*)(s + jj);
                float2 vz = *(const float2*)(s + 16 + jj);
                float2 vn = *(const float2*)(s + 32 + jj);
                hr0 += vr.x; hr1 += vr.y;
                hz0 += vz.x; hz1 += vz.y;
                hn0 += vn.x; hn1 += vn.y;
            }
            float r0 = sigf(igr.x + hr0);
            float r1 = sigf(igr.y + hr1);
            float z0 = sigf(igz.x + hz0);
            float z1 = sigf(igz.y + hz1);
            float n0 = tanhf_fast(ign.x + r0 * (hn0 + bn0));
            float n1 = tanhf_fast(ign.y + r1 * (hn1 + bn1));
            float h0 = (1.0f - z0) * n0 + z0 * hp.x;
            float h1 = (1.0f - z1) * n1 + z1 * hp.y;
            hp = make_float2(h0, h1);

            if (t < T_ - 1) {
                uint2 uv = make_uint2(f2tf(h0), f2tf(h1));
                unsigned* dst = g_h + (size_t)(t & 1) * HB_
                                + (rowbase + bb) * 512 + colbase + jj;
                asm volatile("st.global.cg.v2.u32 [%0], {%1,%2};"
                             :: "l"(dst), "r"(uv.x), "r"(uv.y) : "memory");
            } else {
                *(float2*)(g_hx + (rowbase + bb) * 512 + colbase + jj) =
                    make_float2(h0, h1);
            }
        }

        if (t == T_ - 1) break;
        __syncthreads();                       // all h stores issued
        if (tid == 0) arrive_release(myflag);  // flag value becomes t+1
    }
}

// ===========================================================================
// Kernel 3: out = h_final @ Wlin^T + blin; warp-per-(b,32n), coalesced. FROZEN
// ===========================================================================
__global__ void __launch_bounds__(256) k_out(const float* __restrict__ Wlin,
                                             const float* __restrict__ blin,
                                             float* __restrict__ out) {
    const int wg   = blockIdx.x * 8 + (threadIdx.x >> 5);
    const int lane = threadIdx.x & 31;
    const int b    = wg >> 4;
    const int nb   = (wg & 15) * 32;

    float4 h4[4];
    #pragma unroll
    for (int q = 0; q < 4; q++)
        h4[q] = *(const float4*)(g_hx + b * 512 + q * 128 + lane * 4);

    #pragma unroll 4
    for (int i = 0; i < 32; i++) {
        int n = nb + i;
        const float* wr = Wlin + (size_t)n * 512;
        float s = 0.0f;
        #pragma unroll
        for (int q = 0; q < 4; q++) {
            float4 wv = __ldg((const float4*)(wr + q * 128 + lane * 4));
            s += h4[q].x * wv.x + h4[q].y * wv.y + h4[q].z * wv.z + h4[q].w * wv.w;
        }
        s += __shfl_xor_sync(0xFFFFFFFF, s, 16);
        s += __shfl_xor_sync(0xFFFFFFFF, s, 8);
        s += __shfl_xor_sync(0xFFFFFFFF, s, 4);
        s += __shfl_xor_sync(0xFFFFFFFF, s, 2);
        s += __shfl_xor_sync(0xFFFFFFFF, s, 1);
        if (lane == 0) {
            float v = s + __ldg(blin + n);
            if (n < L_) out[b * L_ + n] = v;
            else        out[(size_t)B_ * L_ + b * L_ + (n - L_)] = v;
        }
    }
}

// ===========================================================================
extern "C" void kernel_launch(void* const* d_in, const int* in_sizes, int n_in,
                              void* d_out, int out_size) {
    const float* x    = (const float*)d_in[0];
    const float* Wih  = (const float*)d_in[1];
    const float* Whh  = (const float*)d_in[2];
    const float* b    = (const float*)d_in[3];
    const float* bn   = (const float*)d_in[4];
    const float* Wlin = (const float*)d_in[5];
    const float* blin = (const float*)d_in[6];
    float* out = (float*)d_out;

    cudaFuncSetAttribute(k_rec, cudaFuncAttributeMaxDynamicSharedMemorySize,
                         SMEM_K2_BYTES);

    dim3 g1(12, 512);
    k_igemm<<<g1, 256>>>(x, Wih, b);
    k_zero<<<1, 256>>>();
    k_rec<<<128, 256, SMEM_K2_BYTES>>>(Whh, bn);
    k_out<<<256, 256>>>(Wlin, blin, out);
}

// round 14
// speedup vs baseline: 1.0663x; 1.0048x over previous
#include <cuda_runtime.h>

#define B_  128
#define T_  512
#define H_  512
#define L_  256
#define HB_ (B_ * H_)

__device__ float    g_ig[(size_t)T_ * B_ * 3 * H_];
__device__ unsigned g_h[2 * HB_];        // step-parity double buffer (tf32 words)
__device__ float    g_hx[HB_];           // exact fp32 h_final
__device__ unsigned long long g_flag[128 * 32];   // 256B spacing

__device__ __forceinline__ unsigned f2tf(float f) {
    unsigned u;
    asm("cvt.rna.tf32.f32 %0, %1;" : "=r"(u) : "f"(f));
    return u;
}
__device__ __forceinline__ void mma8(float c[4],
                                     unsigned a0, unsigned a1, unsigned a2, unsigned a3,
                                     unsigned b0, unsigned b1) {
    asm volatile(
        "mma.sync.aligned.m16n8k8.row.col.f32.tf32.tf32.f32 "
        "{%0,%1,%2,%3}, {%4,%5,%6,%7}, {%8,%9}, {%0,%1,%2,%3};"
        : "+f"(c[0]), "+f"(c[1]), "+f"(c[2]), "+f"(c[3])
        : "r"(a0), "r"(a1), "r"(a2), "r"(a3), "r"(b0), "r"(b1));
}
__device__ __forceinline__ float sigf(float x) { return 1.0f / (1.0f + __expf(-x)); }
__device__ __forceinline__ float tanhf_fast(float x) {
    return 1.0f - __fdividef(2.0f, 1.0f + __expf(2.0f * x));
}
__device__ __forceinline__ unsigned long long arrive_release(unsigned long long* p) {
    unsigned long long old;
    asm volatile("atom.add.release.gpu.u64 %0, [%1], 1;" : "=l"(old) : "l"(p) : "memory");
    return old;
}
__device__ __forceinline__ unsigned long long ld_acquire(const unsigned long long* p) {
    unsigned long long v;
    asm volatile("ld.acquire.gpu.u64 %0, [%1];" : "=l"(v) : "l"(p) : "memory");
    return v;
}

__global__ void k_zero() {
    for (int i = threadIdx.x; i < 128 * 32; i += 256) g_flag[i] = 0ULL;
}

// ===========================================================================
// Kernel 1 v2: IG = X@Wih^T + b. Fat tile 128(M)x256(N), grid (6,512),
//   256 thr, 1 CTA/SM. Warp tile 64x64 (LDS:MMA = 1.0). cp.async
//   double-buffered fp32 staging; cvt.rna.tf32 at fragment load
//   (numerically identical to staging-store cvt).
//   Dynamic SMEM: As[2][128][20] + Bs[2][256][20] = 61440 B.
// ===========================================================================
#define IG2_SMEM_BYTES (15360 * 4)

__global__ void __launch_bounds__(256) k_igemm(const float* __restrict__ x,
                                               const float* __restrict__ Wih,
                                               const float* __restrict__ bias) {
    extern __shared__ float sm1[];
    // buf0: A @0 (2560 w), B @2560 (5120 w); buf1: A @7680, B @10240
    const int t   = blockIdx.y;
    const int n0  = blockIdx.x * 256;
    const int tid = threadIdx.x;
    const int w    = tid >> 5;
    const int lane = tid & 31;
    const int gid  = lane >> 2;
    const int tig  = lane & 3;
    const int mrow = (w >> 2) * 64;   // 0 or 64
    const int ncol = (w & 3) * 64;    // 0,64,128,192

    const int lr  = tid >> 2;         // staging row base
    const int lc4 = (tid & 3) * 4;    // staging col word

    auto issue = [&](int k0, int buf) {
        float* Ab = sm1 + buf * 7680;
        float* Bb = sm1 + buf * 7680 + 2560;
        #pragma unroll
        for (int it = 0; it < 2; it++) {          // A: 128 rows
            int r = lr + it * 64;
            const float* ga = x + ((size_t)r * 512 + t) * 512 + k0 + lc4;
            unsigned sa = (unsigned)__cvta_generic_to_shared(Ab + r * 20 + lc4);
            asm volatile("cp.async.cg.shared.global [%0], [%1], 16;"
                         :: "r"(sa), "l"(ga));
        }
        #pragma unroll
        for (int it = 0; it < 4; it++) {          // B: 256 rows
            int r = lr + it * 64;
            const float* gb = Wih + (size_t)(n0 + r) * 512 + k0 + lc4;
            unsigned sb = (unsigned)__cvta_generic_to_shared(Bb + r * 20 + lc4);
            asm volatile("cp.async.cg.shared.global [%0], [%1], 16;"
                         :: "r"(sb), "l"(gb));
        }
        asm volatile("cp.async.commit_group;");
    };

    float acc[4][8][4];
    #pragma unroll
    for (int i = 0; i < 4; i++)
        #pragma unroll
        for (int j = 0; j < 8; j++)
            #pragma unroll
            for (int q = 0; q < 4; q++) acc[i][j][q] = 0.0f;

    issue(0, 0);

    for (int c = 0; c < 32; c++) {
        asm volatile("cp.async.wait_group 0;" ::: "memory");
        __syncthreads();
        if (c < 31) issue((c + 1) * 16, (c + 1) & 1);
        const float* A  = sm1 + (c & 1) * 7680;
        const float* Bb = sm1 + (c & 1) * 7680 + 2560;

        #pragma unroll
        for (int ks = 0; ks < 2; ks++) {
            const int kb = ks * 8;
            unsigned a[4][4];
            #pragma unroll
            for (int mt = 0; mt < 4; mt++) {
                int r = mrow + mt * 16 + gid;
                a[mt][0] = f2tf(A[r * 20 + kb + tig]);
                a[mt][1] = f2tf(A[(r + 8) * 20 + kb + tig]);
                a[mt][2] = f2tf(A[r * 20 + kb + tig + 4]);
                a[mt][3] = f2tf(A[(r + 8) * 20 + kb + tig + 4]);
            }
            #pragma unroll
            for (int nt = 0; nt < 8; nt++) {
                int n = ncol + nt * 8 + gid;
                unsigned b0 = f2tf(Bb[n * 20 + kb + tig]);
                unsigned b1 = f2tf(Bb[n * 20 + kb + tig + 4]);
                #pragma unroll
                for (int mt = 0; mt < 4; mt++)
                    mma8(acc[mt][nt], a[mt][0], a[mt][1], a[mt][2], a[mt][3], b0, b1);
            }
        }
    }

    #pragma unroll
    for (int mt = 0; mt < 4; mt++) {
        #pragma unroll
        for (int nt = 0; nt < 8; nt++) {
            int r0 = mrow + mt * 16 + gid;
            int c0 = n0 + ncol + nt * 8 + 2 * tig;
            float bv0 = __ldg(bias + c0);
            float bv1 = __ldg(bias + c0 + 1);
            size_t base0 = ((size_t)t * 128 + r0) * 1536 + c0;
            size_t base1 = ((size_t)t * 128 + r0 + 8) * 1536 + c0;
            *(float2*)&g_ig[base0] = make_float2(acc[mt][nt][0] + bv0, acc[mt][nt][1] + bv1);
            *(float2*)&g_ig[base1] = make_float2(acc[mt][nt][2] + bv0, acc[mt][nt][3] + bv1);
        }
    }
}

// ===========================================================================
// Kernel 2: persistent GRU recurrence (FROZEN from round 13: best known)
// ===========================================================================
#define WS_PITCH 516
#define SG_PITCH 52
#define SMEM_K2_BYTES (80 * WS_PITCH * 4)

__global__ void __launch_bounds__(256, 1) k_rec(const float* __restrict__ Whh,
                                                const float* __restrict__ bn) {
    extern __shared__ unsigned smem[];
    unsigned* Ws = smem;
    unsigned* Hs = smem + 48 * WS_PITCH;
    float*    Sg = (float*)smem;

    const int tid  = threadIdx.x;
    const int lane = tid & 31;
    const int w    = tid >> 5;
    const int gid  = lane >> 2;
    const int tig  = lane & 3;
    const int mg   = blockIdx.x >> 5;
    const int cg   = blockIdx.x & 31;
    const int rowbase = mg * 32;
    const int colbase = cg * 16;

    for (int i = tid; i < 48 * 128; i += 256) {
        int lr   = i >> 7;
        int c4   = (i & 127) * 4;
        int grow = (lr >> 4) * 512 + colbase + (lr & 15);
        float4 v = *(const float4*)(Whh + (size_t)grow * 512 + c4);
        uint4 u = make_uint4(f2tf(v.x), f2tf(v.y), f2tf(v.z), f2tf(v.w));
        *(uint4*)&Ws[lr * WS_PITCH + c4] = u;
    }
    for (int i = tid; i < 32 * WS_PITCH; i += 256) Hs[i] = 0u;
    __syncthreads();

    const int kbase = w * 64;
    unsigned wf[8][6][2];
    #pragma unroll
    for (int kt = 0; kt < 8; kt++)
        #pragma unroll
        for (int nt = 0; nt < 6; nt++) {
            int base = (nt * 8 + gid) * WS_PITCH + kbase + kt * 8 + tig;
            wf[kt][nt][0] = Ws[base];
            wf[kt][nt][1] = Ws[base + 4];
        }
    __syncthreads();

    const int bb = tid >> 3;
    const int jj = (tid * 2) & 15;
    const float bn0 = __ldg(bn + colbase + jj);
    const float bn1 = __ldg(bn + colbase + jj + 1);
    float2 hp = make_float2(0.0f, 0.0f);

    float* Sgw = Sg + w * 32 * SG_PITCH;
    unsigned long long* myflag = &g_flag[(mg * 32 + cg) * 32];
    const unsigned long long* pf = &g_flag[(mg * 32 + w * 4 + (lane & 3)) * 32];
    const int rs_half = lane >> 4;
    const int rs_c4   = (lane & 15) * 4;

    for (int t = 0; t < T_; t++) {
        const float* igb = g_ig + ((size_t)t * 128 + rowbase + bb) * 1536 + colbase + jj;
        float2 igr = __ldg((const float2*)(igb));
        float2 igz = __ldg((const float2*)(igb + 512));
        float2 ign = __ldg((const float2*)(igb + 1024));

        if (t > 0) {
            if (lane < 4) {
                while (ld_acquire(pf) < (unsigned long long)t) { }
            }
            __syncwarp();
            const unsigned* hsrc = g_h + (size_t)((t - 1) & 1) * HB_;
            #pragma unroll
            for (int rr = 0; rr < 16; rr++) {
                int row = rr * 2 + rs_half;
                const uint4* src = (const uint4*)(hsrc + (rowbase + row) * 512 + kbase + rs_c4);
                uint4 v;
                asm volatile("ld.global.cg.v4.u32 {%0,%1,%2,%3}, [%4];"
                             : "=r"(v.x), "=r"(v.y), "=r"(v.z), "=r"(v.w) : "l"(src));
                *(uint4*)&Hs[row * WS_PITCH + kbase + rs_c4] = v;
            }
        }

        float c[2][6][4];
        #pragma unroll
        for (int m = 0; m < 2; m++)
            #pragma unroll
            for (int n = 0; n < 6; n++)
                #pragma unroll
                for (int q = 0; q < 4; q++) c[m][n][q] = 0.0f;

        #pragma unroll
        for (int kt = 0; kt < 8; kt++) {
            const int kb = kbase + kt * 8;
            unsigned a[2][4];
            #pragma unroll
            for (int m = 0; m < 2; m++) {
                int r = m * 16 + gid;
                a[m][0] = Hs[r * WS_PITCH + kb + tig];
                a[m][1] = Hs[(r + 8) * WS_PITCH + kb + tig];
                a[m][2] = Hs[r * WS_PITCH + kb + tig + 4];
                a[m][3] = Hs[(r + 8) * WS_PITCH + kb + tig + 4];
            }
            #pragma unroll
            for (int n = 0; n < 6; n++) {
                mma8(c[0][n], a[0][0], a[0][1], a[0][2], a[0][3], wf[kt][n][0], wf[kt][n][1]);
                mma8(c[1][n], a[1][0], a[1][1], a[1][2], a[1][3], wf[kt][n][0], wf[kt][n][1]);
            }
        }

        #pragma unroll
        for (int m = 0; m < 2; m++) {
            int r0 = m * 16 + gid, r1 = r0 + 8;
            #pragma unroll
            for (int n = 0; n < 6; n++) {
                int cb = n * 8 + 2 * tig;
                *(float2*)&Sgw[r0 * SG_PITCH + cb] = make_float2(c[m][n][0], c[m][n][1]);
                *(float2*)&Sgw[r1 * SG_PITCH + cb] = make_float2(c[m][n][2], c[m][n][3]);
            }
        }
        __syncthreads();

        {
            float hr0 = 0.f, hr1 = 0.f, hz0 = 0.f, hz1 = 0.f, hn0 = 0.f, hn1 = 0.f;
            #pragma unroll
            for (int k = 0; k < 8; k++) {
                const float* s = Sg + k * 32 * SG_PITCH + bb * SG_PITCH;
                float2 vr = *(const float2*)(s + jj);
                float2 vz = *(const float2*)(s + 16 + jj);
                float2 vn = *(const float2*)(s + 32 + jj);
                hr0 += vr.x; hr1 += vr.y;
                hz0 += vz.x; hz1 += vz.y;
                hn0 += vn.x; hn1 += vn.y;
            }
            float r0 = sigf(igr.x + hr0);
            float r1 = sigf(igr.y + hr1);
            float z0 = sigf(igz.x + hz0);
            float z1 = sigf(igz.y + hz1);
            float n0 = tanhf_fast(ign.x + r0 * (hn0 + bn0));
            float n1 = tanhf_fast(ign.y + r1 * (hn1 + bn1));
            float h0 = (1.0f - z0) * n0 + z0 * hp.x;
            float h1 = (1.0f - z1) * n1 + z1 * hp.y;
            hp = make_float2(h0, h1);

            if (t < T_ - 1) {
                uint2 uv = make_uint2(f2tf(h0), f2tf(h1));
                unsigned* dst = g_h + (size_t)(t & 1) * HB_
                                + (rowbase + bb) * 512 + colbase + jj;
                asm volatile("st.global.cg.v2.u32 [%0], {%1,%2};"
                             :: "l"(dst), "r"(uv.x), "r"(uv.y) : "memory");
            } else {
                *(float2*)(g_hx + (rowbase + bb) * 512 + colbase + jj) =
                    make_float2(h0, h1);
            }
        }

        if (t == T_ - 1) break;
        __syncthreads();
        if (tid == 0) arrive_release(myflag);
    }
}

// ===========================================================================
// Kernel 3: out = h_final @ Wlin^T + blin (FROZEN)
// ===========================================================================
__global__ void __launch_bounds__(256) k_out(const float* __restrict__ Wlin,
                                             const float* __restrict__ blin,
                                             float* __restrict__ out) {
    const int wg   = blockIdx.x * 8 + (threadIdx.x >> 5);
    const int lane = threadIdx.x & 31;
    const int b    = wg >> 4;
    const int nb   = (wg & 15) * 32;

    float4 h4[4];
    #pragma unroll
    for (int q = 0; q < 4; q++)
        h4[q] = *(const float4*)(g_hx + b * 512 + q * 128 + lane * 4);

    #pragma unroll 4
    for (int i = 0; i < 32; i++) {
        int n = nb + i;
        const float* wr = Wlin + (size_t)n * 512;
        float s = 0.0f;
        #pragma unroll
        for (int q = 0; q < 4; q++) {
            float4 wv = __ldg((const float4*)(wr + q * 128 + lane * 4));
            s += h4[q].x * wv.x + h4[q].y * wv.y + h4[q].z * wv.z + h4[q].w * wv.w;
        }
        s += __shfl_xor_sync(0xFFFFFFFF, s, 16);
        s += __shfl_xor_sync(0xFFFFFFFF, s, 8);
        s += __shfl_xor_sync(0xFFFFFFFF, s, 4);
        s += __shfl_xor_sync(0xFFFFFFFF, s, 2);
        s += __shfl_xor_sync(0xFFFFFFFF, s, 1);
        if (lane == 0) {
            float v = s + __ldg(blin + n);
            if (n < L_) out[b * L_ + n] = v;
            else        out[(size_t)B_ * L_ + b * L_ + (n - L_)] = v;
        }
    }
}

// ===========================================================================
extern "C" void kernel_launch(void* const* d_in, const int* in_sizes, int n_in,
                              void* d_out, int out_size) {
    const float* x    = (const float*)d_in[0];
    const float* Wih  = (const float*)d_in[1];
    const float* Whh  = (const float*)d_in[2];
    const float* b    = (const float*)d_in[3];
    const float* bn   = (const float*)d_in[4];
    const float* Wlin = (const float*)d_in[5];
    const float* blin = (const float*)d_in[6];
    float* out = (float*)d_out;

    cudaFuncSetAttribute(k_igemm, cudaFuncAttributeMaxDynamicSharedMemorySize,
                         IG2_SMEM_BYTES);
    cudaFuncSetAttribute(k_rec, cudaFuncAttributeMaxDynamicSharedMemorySize,
                         SMEM_K2_BYTES);

    dim3 g1(6, 512);
    k_igemm<<<g1, 256, IG2_SMEM_BYTES>>>(x, Wih, b);
    k_zero<<<1, 256>>>();
    k_rec<<<128, 256, SMEM_K2_BYTES>>>(Whh, bn);
    k_out<<<256, 256>>>(Wlin, blin, out);
}

// round 15
// speedup vs baseline: 1.1575x; 1.0856x over previous
#include <cuda_runtime.h>
#include <cuda_fp16.h>

#define B_  128
#define T_  512
#define H_  512
#define L_  256
#define HB_ (B_ * H_)

__device__ float    g_ig[(size_t)T_ * B_ * 3 * H_];
__device__ unsigned g_h[2 * HB_];        // step-parity double buffer (tf32 words)
__device__ float    g_hx[HB_];           // exact fp32 h_final
__device__ unsigned long long g_flag[128 * 32];   // 256B spacing

__device__ __forceinline__ unsigned f2tf(float f) {
    unsigned u;
    asm("cvt.rna.tf32.f32 %0, %1;" : "=r"(u) : "f"(f));
    return u;
}
__device__ __forceinline__ unsigned pack_h2(float x, float y) {
    __half2 h = __floats2half2_rn(x, y);
    return *(unsigned*)&h;
}
__device__ __forceinline__ void mma8(float c[4],
                                     unsigned a0, unsigned a1, unsigned a2, unsigned a3,
                                     unsigned b0, unsigned b1) {
    asm volatile(
        "mma.sync.aligned.m16n8k8.row.col.f32.tf32.tf32.f32 "
        "{%0,%1,%2,%3}, {%4,%5,%6,%7}, {%8,%9}, {%0,%1,%2,%3};"
        : "+f"(c[0]), "+f"(c[1]), "+f"(c[2]), "+f"(c[3])
        : "r"(a0), "r"(a1), "r"(a2), "r"(a3), "r"(b0), "r"(b1));
}
__device__ __forceinline__ void mma16(float c[4],
                                      unsigned a0, unsigned a1, unsigned a2, unsigned a3,
                                      unsigned b0, unsigned b1) {
    asm volatile(
        "mma.sync.aligned.m16n8k16.row.col.f32.f16.f16.f32 "
        "{%0,%1,%2,%3}, {%4,%5,%6,%7}, {%8,%9}, {%0,%1,%2,%3};"
        : "+f"(c[0]), "+f"(c[1]), "+f"(c[2]), "+f"(c[3])
        : "r"(a0), "r"(a1), "r"(a2), "r"(a3), "r"(b0), "r"(b1));
}
__device__ __forceinline__ float sigf(float x) { return 1.0f / (1.0f + __expf(-x)); }
__device__ __forceinline__ float tanhf_fast(float x) {
    return 1.0f - __fdividef(2.0f, 1.0f + __expf(2.0f * x));
}
__device__ __forceinline__ unsigned long long arrive_release(unsigned long long* p) {
    unsigned long long old;
    asm volatile("atom.add.release.gpu.u64 %0, [%1], 1;" : "=l"(old) : "l"(p) : "memory");
    return old;
}
__device__ __forceinline__ unsigned long long ld_acquire(const unsigned long long* p) {
    unsigned long long v;
    asm volatile("ld.acquire.gpu.u64 %0, [%1];" : "=l"(v) : "l"(p) : "memory");
    return v;
}

__global__ void k_zero() {
    for (int i = threadIdx.x; i < 128 * 32; i += 256) g_flag[i] = 0ULL;
}

// ===========================================================================
// Kernel 1 v3 (fp16 HMMA): IG = X@Wih^T + b.
//   Tile 128x128, grid (12,512), 256 thr, warp tile 64x32, k-chunk 16.
//   ONE m16n8k16 per (mt,nt) per chunk (2x MACs/instr vs tf32 m16n8k8).
//   SMEM tiles: packed half2 words, pitch 12 (conflict-free fragments).
//   fp32 accumulate; fp16 input rounding == tf32 mantissa width.
// ===========================================================================
__global__ void __launch_bounds__(256) k_igemm(const float* __restrict__ x,
                                               const float* __restrict__ Wih,
                                               const float* __restrict__ bias) {
    __shared__ unsigned As[128][12];   // 16 halves (8 words) + 4 pad per row
    __shared__ unsigned Bs[128][12];

    const int t   = blockIdx.y;
    const int n0  = blockIdx.x * 128;
    const int tid = threadIdx.x;
    const int w    = tid >> 5;
    const int lane = tid & 31;
    const int gid  = lane >> 2;
    const int tig  = lane & 3;
    const int mrow = (w >> 2) * 64;
    const int ncol = (w & 3) * 32;

    float acc[4][4][4];
    #pragma unroll
    for (int i = 0; i < 4; i++)
        #pragma unroll
        for (int j = 0; j < 4; j++)
            #pragma unroll
            for (int q = 0; q < 4; q++) acc[i][j][q] = 0.0f;

    for (int k0 = 0; k0 < 512; k0 += 16) {
        // Stage A and B as packed half2 (2 slots each per thread)
        #pragma unroll
        for (int it = 0; it < 2; it++) {
            int i  = tid + it * 256;          // float4 slot 0..511
            int r  = i >> 2;
            int c  = i & 3;                   // word-pair index
            float4 va = *(const float4*)(x + ((size_t)r * 512 + t) * 512 + k0 + c * 4);
            As[r][2 * c]     = pack_h2(va.x, va.y);
            As[r][2 * c + 1] = pack_h2(va.z, va.w);
            float4 vb = *(const float4*)(Wih + (size_t)(n0 + r) * 512 + k0 + c * 4);
            Bs[r][2 * c]     = pack_h2(vb.x, vb.y);
            Bs[r][2 * c + 1] = pack_h2(vb.z, vb.w);
        }
        __syncthreads();

        // One m16n8k16 per (mt,nt): a0=(r,2tig..+1) a1=(r+8,..) a2=(r,2tig+8..+9) a3=(r+8,..)
        unsigned a[4][4];
        #pragma unroll
        for (int mt = 0; mt < 4; mt++) {
            int r = mrow + mt * 16 + gid;
            a[mt][0] = As[r][tig];
            a[mt][1] = As[r + 8][tig];
            a[mt][2] = As[r][tig + 4];
            a[mt][3] = As[r + 8][tig + 4];
        }
        #pragma unroll
        for (int nt = 0; nt < 4; nt++) {
            int n = ncol + nt * 8 + gid;
            unsigned b0 = Bs[n][tig];
            unsigned b1 = Bs[n][tig + 4];
            #pragma unroll
            for (int mt = 0; mt < 4; mt++)
                mma16(acc[mt][nt], a[mt][0], a[mt][1], a[mt][2], a[mt][3], b0, b1);
        }
        __syncthreads();
    }

    #pragma unroll
    for (int mt = 0; mt < 4; mt++) {
        #pragma unroll
        for (int nt = 0; nt < 4; nt++) {
            int r0 = mrow + mt * 16 + gid;
            int c0 = n0 + ncol + nt * 8 + 2 * tig;
            float bv0 = __ldg(bias + c0);
            float bv1 = __ldg(bias + c0 + 1);
            size_t base0 = ((size_t)t * 128 + r0) * 1536 + c0;
            size_t base1 = ((size_t)t * 128 + r0 + 8) * 1536 + c0;
            *(float2*)&g_ig[base0] = make_float2(acc[mt][nt][0] + bv0, acc[mt][nt][1] + bv1);
            *(float2*)&g_ig[base1] = make_float2(acc[mt][nt][2] + bv0, acc[mt][nt][3] + bv1);
        }
    }
}

// ===========================================================================
// Kernel 2: persistent GRU recurrence (FROZEN from round 13: best known)
// ===========================================================================
#define WS_PITCH 516
#define SG_PITCH 52
#define SMEM_K2_BYTES (80 * WS_PITCH * 4)

__global__ void __launch_bounds__(256, 1) k_rec(const float* __restrict__ Whh,
                                                const float* __restrict__ bn) {
    extern __shared__ unsigned smem[];
    unsigned* Ws = smem;
    unsigned* Hs = smem + 48 * WS_PITCH;
    float*    Sg = (float*)smem;

    const int tid  = threadIdx.x;
    const int lane = tid & 31;
    const int w    = tid >> 5;
    const int gid  = lane >> 2;
    const int tig  = lane & 3;
    const int mg   = blockIdx.x >> 5;
    const int cg   = blockIdx.x & 31;
    const int rowbase = mg * 32;
    const int colbase = cg * 16;

    for (int i = tid; i < 48 * 128; i += 256) {
        int lr   = i >> 7;
        int c4   = (i & 127) * 4;
        int grow = (lr >> 4) * 512 + colbase + (lr & 15);
        float4 v = *(const float4*)(Whh + (size_t)grow * 512 + c4);
        uint4 u = make_uint4(f2tf(v.x), f2tf(v.y), f2tf(v.z), f2tf(v.w));
        *(uint4*)&Ws[lr * WS_PITCH + c4] = u;
    }
    for (int i = tid; i < 32 * WS_PITCH; i += 256) Hs[i] = 0u;
    __syncthreads();

    const int kbase = w * 64;
    unsigned wf[8][6][2];
    #pragma unroll
    for (int kt = 0; kt < 8; kt++)
        #pragma unroll
        for (int nt = 0; nt < 6; nt++) {
            int base = (nt * 8 + gid) * WS_PITCH + kbase + kt * 8 + tig;
            wf[kt][nt][0] = Ws[base];
            wf[kt][nt][1] = Ws[base + 4];
        }
    __syncthreads();

    const int bb = tid >> 3;
    const int jj = (tid * 2) & 15;
    const float bn0 = __ldg(bn + colbase + jj);
    const float bn1 = __ldg(bn + colbase + jj + 1);
    float2 hp = make_float2(0.0f, 0.0f);

    float* Sgw = Sg + w * 32 * SG_PITCH;
    unsigned long long* myflag = &g_flag[(mg * 32 + cg) * 32];
    const unsigned long long* pf = &g_flag[(mg * 32 + w * 4 + (lane & 3)) * 32];
    const int rs_half = lane >> 4;
    const int rs_c4   = (lane & 15) * 4;

    for (int t = 0; t < T_; t++) {
        const float* igb = g_ig + ((size_t)t * 128 + rowbase + bb) * 1536 + colbase + jj;
        float2 igr = __ldg((const float2*)(igb));
        float2 igz = __ldg((const float2*)(igb + 512));
        float2 ign = __ldg((const float2*)(igb + 1024));

        if (t > 0) {
            if (lane < 4) {
                while (ld_acquire(pf) < (unsigned long long)t) { }
            }
            __syncwarp();
            const unsigned* hsrc = g_h + (size_t)((t - 1) & 1) * HB_;
            #pragma unroll
            for (int rr = 0; rr < 16; rr++) {
                int row = rr * 2 + rs_half;
                const uint4* src = (const uint4*)(hsrc + (rowbase + row) * 512 + kbase + rs_c4);
                uint4 v;
                asm volatile("ld.global.cg.v4.u32 {%0,%1,%2,%3}, [%4];"
                             : "=r"(v.x), "=r"(v.y), "=r"(v.z), "=r"(v.w) : "l"(src));
                *(uint4*)&Hs[row * WS_PITCH + kbase + rs_c4] = v;
            }
        }

        float c[2][6][4];
        #pragma unroll
        for (int m = 0; m < 2; m++)
            #pragma unroll
            for (int n = 0; n < 6; n++)
                #pragma unroll
                for (int q = 0; q < 4; q++) c[m][n][q] = 0.0f;

        #pragma unroll
        for (int kt = 0; kt < 8; kt++) {
            const int kb = kbase + kt * 8;
            unsigned a[2][4];
            #pragma unroll
            for (int m = 0; m < 2; m++) {
                int r = m * 16 + gid;
                a[m][0] = Hs[r * WS_PITCH + kb + tig];
                a[m][1] = Hs[(r + 8) * WS_PITCH + kb + tig];
                a[m][2] = Hs[r * WS_PITCH + kb + tig + 4];
                a[m][3] = Hs[(r + 8) * WS_PITCH + kb + tig + 4];
            }
            #pragma unroll
            for (int n = 0; n < 6; n++) {
                mma8(c[0][n], a[0][0], a[0][1], a[0][2], a[0][3], wf[kt][n][0], wf[kt][n][1]);
                mma8(c[1][n], a[1][0], a[1][1], a[1][2], a[1][3], wf[kt][n][0], wf[kt][n][1]);
            }
        }

        #pragma unroll
        for (int m = 0; m < 2; m++) {
            int r0 = m * 16 + gid, r1 = r0 + 8;
            #pragma unroll
            for (int n = 0; n < 6; n++) {
                int cb = n * 8 + 2 * tig;
                *(float2*)&Sgw[r0 * SG_PITCH + cb] = make_float2(c[m][n][0], c[m][n][1]);
                *(float2*)&Sgw[r1 * SG_PITCH + cb] = make_float2(c[m][n][2], c[m][n][3]);
            }
        }
        __syncthreads();

        {
            float hr0 = 0.f, hr1 = 0.f, hz0 = 0.f, hz1 = 0.f, hn0 = 0.f, hn1 = 0.f;
            #pragma unroll
            for (int k = 0; k < 8; k++) {
                const float* s = Sg + k * 32 * SG_PITCH + bb * SG_PITCH;
                float2 vr = *(const float2*)(s + jj);
                float2 vz = *(const float2*)(s + 16 + jj);
                float2 vn = *(const float2*)(s + 32 + jj);
                hr0 += vr.x; hr1 += vr.y;
                hz0 += vz.x; hz1 += vz.y;
                hn0 += vn.x; hn1 += vn.y;
            }
            float r0 = sigf(igr.x + hr0);
            float r1 = sigf(igr.y + hr1);
            float z0 = sigf(igz.x + hz0);
            float z1 = sigf(igz.y + hz1);
            float n0 = tanhf_fast(ign.x + r0 * (hn0 + bn0));
            float n1 = tanhf_fast(ign.y + r1 * (hn1 + bn1));
            float h0 = (1.0f - z0) * n0 + z0 * hp.x;
            float h1 = (1.0f - z1) * n1 + z1 * hp.y;
            hp = make_float2(h0, h1);

            if (t < T_ - 1) {
                uint2 uv = make_uint2(f2tf(h0), f2tf(h1));
                unsigned* dst = g_h + (size_t)(t & 1) * HB_
                                + (rowbase + bb) * 512 + colbase + jj;
                asm volatile("st.global.cg.v2.u32 [%0], {%1,%2};"
                             :: "l"(dst), "r"(uv.x), "r"(uv.y) : "memory");
            } else {
                *(float2*)(g_hx + (rowbase + bb) * 512 + colbase + jj) =
                    make_float2(h0, h1);
            }
        }

        if (t == T_ - 1) break;
        __syncthreads();
        if (tid == 0) arrive_release(myflag);
    }
}

// ===========================================================================
// Kernel 3: out = h_final @ Wlin^T + blin (FROZEN)
// ===========================================================================
__global__ void __launch_bounds__(256) k_out(const float* __restrict__ Wlin,
                                             const float* __restrict__ blin,
                                             float* __restrict__ out) {
    const int wg   = blockIdx.x * 8 + (threadIdx.x >> 5);
    const int lane = threadIdx.x & 31;
    const int b    = wg >> 4;
    const int nb   = (wg & 15) * 32;

    float4 h4[4];
    #pragma unroll
    for (int q = 0; q < 4; q++)
        h4[q] = *(const float4*)(g_hx + b * 512 + q * 128 + lane * 4);

    #pragma unroll 4
    for (int i = 0; i < 32; i++) {
        int n = nb + i;
        const float* wr = Wlin + (size_t)n * 512;
        float s = 0.0f;
        #pragma unroll
        for (int q = 0; q < 4; q++) {
            float4 wv = __ldg((const float4*)(wr + q * 128 + lane * 4));
            s += h4[q].x * wv.x + h4[q].y * wv.y + h4[q].z * wv.z + h4[q].w * wv.w;
        }
        s += __shfl_xor_sync(0xFFFFFFFF, s, 16);
        s += __shfl_xor_sync(0xFFFFFFFF, s, 8);
        s += __shfl_xor_sync(0xFFFFFFFF, s, 4);
        s += __shfl_xor_sync(0xFFFFFFFF, s, 2);
        s += __shfl_xor_sync(0xFFFFFFFF, s, 1);
        if (lane == 0) {
            float v = s + __ldg(blin + n);
            if (n < L_) out[b * L_ + n] = v;
            else        out[(size_t)B_ * L_ + b * L_ + (n - L_)] = v;
        }
    }
}

// ===========================================================================
extern "C" void kernel_launch(void* const* d_in, const int* in_sizes, int n_in,
                              void* d_out, int out_size) {
    const float* x    = (const float*)d_in[0];
    const float* Wih  = (const float*)d_in[1];
    const float* Whh  = (const float*)d_in[2];
    const float* b    = (const float*)d_in[3];
    const float* bn   = (const float*)d_in[4];
    const float* Wlin = (const float*)d_in[5];
    const float* blin = (const float*)d_in[6];
    float* out = (float*)d_out;

    cudaFuncSetAttribute(k_rec, cudaFuncAttributeMaxDynamicSharedMemorySize,
                         SMEM_K2_BYTES);

    dim3 g1(12, 512);
    k_igemm<<<g1, 256>>>(x, Wih, b);
    k_zero<<<1, 256>>>();
    k_rec<<<128, 256, SMEM_K2_BYTES>>>(Whh, bn);
    k_out<<<256, 256>>>(Wlin, blin, out);
}

// round 16
// speedup vs baseline: 1.3152x; 1.1362x over previous
#include <cuda_runtime.h>
#include <cuda_fp16.h>

#define B_  128
#define T_  512
#define H_  512
#define L_  256
#define HW2_ 256                 // h row width in half2 words
#define HB2_ (B_ * HW2_)         // one h buffer in words (32768)

__device__ float    g_ig[(size_t)T_ * B_ * 3 * H_];
__device__ unsigned g_h[2 * HB2_];       // step-parity double buffer (half2 words)
__device__ float    g_hx[B_ * H_];       // exact fp32 h_final
__device__ unsigned long long g_flag[128 * 32];   // 256B spacing

__device__ __forceinline__ unsigned pack_h2(float x, float y) {
    __half2 h = __floats2half2_rn(x, y);
    return *(unsigned*)&h;
}
__device__ __forceinline__ void mma16(float c[4],
                                      unsigned a0, unsigned a1, unsigned a2, unsigned a3,
                                      unsigned b0, unsigned b1) {
    asm volatile(
        "mma.sync.aligned.m16n8k16.row.col.f32.f16.f16.f32 "
        "{%0,%1,%2,%3}, {%4,%5,%6,%7}, {%8,%9}, {%0,%1,%2,%3};"
        : "+f"(c[0]), "+f"(c[1]), "+f"(c[2]), "+f"(c[3])
        : "r"(a0), "r"(a1), "r"(a2), "r"(a3), "r"(b0), "r"(b1));
}
__device__ __forceinline__ float sigf(float x) { return 1.0f / (1.0f + __expf(-x)); }
__device__ __forceinline__ float tanhf_fast(float x) {
    return 1.0f - __fdividef(2.0f, 1.0f + __expf(2.0f * x));
}
__device__ __forceinline__ unsigned long long arrive_release(unsigned long long* p) {
    unsigned long long old;
    asm volatile("atom.add.release.gpu.u64 %0, [%1], 1;" : "=l"(old) : "l"(p) : "memory");
    return old;
}
__device__ __forceinline__ unsigned long long ld_acquire(const unsigned long long* p) {
    unsigned long long v;
    asm volatile("ld.acquire.gpu.u64 %0, [%1];" : "=l"(v) : "l"(p) : "memory");
    return v;
}

__global__ void k_zero() {
    for (int i = threadIdx.x; i < 128 * 32; i += 256) g_flag[i] = 0ULL;
}

// ===========================================================================
// Kernel 1 (fp16 HMMA, FROZEN round-15: ~645us): IG = X@Wih^T + b
// ===========================================================================
__global__ void __launch_bounds__(256) k_igemm(const float* __restrict__ x,
                                               const float* __restrict__ Wih,
                                               const float* __restrict__ bias) {
    __shared__ unsigned As[128][12];
    __shared__ unsigned Bs[128][12];

    const int t   = blockIdx.y;
    const int n0  = blockIdx.x * 128;
    const int tid = threadIdx.x;
    const int w    = tid >> 5;
    const int lane = tid & 31;
    const int gid  = lane >> 2;
    const int tig  = lane & 3;
    const int mrow = (w >> 2) * 64;
    const int ncol = (w & 3) * 32;

    float acc[4][4][4];
    #pragma unroll
    for (int i = 0; i < 4; i++)
        #pragma unroll
        for (int j = 0; j < 4; j++)
            #pragma unroll
            for (int q = 0; q < 4; q++) acc[i][j][q] = 0.0f;

    for (int k0 = 0; k0 < 512; k0 += 16) {
        #pragma unroll
        for (int it = 0; it < 2; it++) {
            int i  = tid + it * 256;
            int r  = i >> 2;
            int c  = i & 3;
            float4 va = *(const float4*)(x + ((size_t)r * 512 + t) * 512 + k0 + c * 4);
            As[r][2 * c]     = pack_h2(va.x, va.y);
            As[r][2 * c + 1] = pack_h2(va.z, va.w);
            float4 vb = *(const float4*)(Wih + (size_t)(n0 + r) * 512 + k0 + c * 4);
            Bs[r][2 * c]     = pack_h2(vb.x, vb.y);
            Bs[r][2 * c + 1] = pack_h2(vb.z, vb.w);
        }
        __syncthreads();

        unsigned a[4][4];
        #pragma unroll
        for (int mt = 0; mt < 4; mt++) {
            int r = mrow + mt * 16 + gid;
            a[mt][0] = As[r][tig];
            a[mt][1] = As[r + 8][tig];
            a[mt][2] = As[r][tig + 4];
            a[mt][3] = As[r + 8][tig + 4];
        }
        #pragma unroll
        for (int nt = 0; nt < 4; nt++) {
            int n = ncol + nt * 8 + gid;
            unsigned b0 = Bs[n][tig];
            unsigned b1 = Bs[n][tig + 4];
            #pragma unroll
            for (int mt = 0; mt < 4; mt++)
                mma16(acc[mt][nt], a[mt][0], a[mt][1], a[mt][2], a[mt][3], b0, b1);
        }
        __syncthreads();
    }

    #pragma unroll
    for (int mt = 0; mt < 4; mt++) {
        #pragma unroll
        for (int nt = 0; nt < 4; nt++) {
            int r0 = mrow + mt * 16 + gid;
            int c0 = n0 + ncol + nt * 8 + 2 * tig;
            float bv0 = __ldg(bias + c0);
            float bv1 = __ldg(bias + c0 + 1);
            size_t base0 = ((size_t)t * 128 + r0) * 1536 + c0;
            size_t base1 = ((size_t)t * 128 + r0 + 8) * 1536 + c0;
            *(float2*)&g_ig[base0] = make_float2(acc[mt][nt][0] + bv0, acc[mt][nt][1] + bv1);
            *(float2*)&g_ig[base1] = make_float2(acc[mt][nt][2] + bv0, acc[mt][nt][3] + bv1);
        }
    }
}

// ===========================================================================
// Kernel 2 (fp16 MMA): persistent GRU recurrence, R13 sync structure.
//   Hs/Ws/g_h packed half2. Warp K-slice = 4 chunks of k=16.
//   32 LDS + 48 mma16 per step (was 64 LDS + 96 mma8).
// ===========================================================================
#define HS_PITCH 260               // 256 words + 4 pad; (gid*260+tig)%32 distinct
#define SG_PITCH 52
#define SG_WORDS (8 * 32 * SG_PITCH)          // 13312
#define K2_HS_OFF SG_WORDS                    // Hs after Sg region
#define SMEM_K2_BYTES ((SG_WORDS + 32 * HS_PITCH) * 4)   // 86528 B

__global__ void __launch_bounds__(256, 1) k_rec(const float* __restrict__ Whh,
                                                const float* __restrict__ bn) {
    extern __shared__ unsigned smem[];
    unsigned* Ws = smem;                       // [48][260] init only (12480 w < SG_WORDS)
    unsigned* Hs = smem + K2_HS_OFF;           // [32][260] half2 h tile
    float*    Sg = (float*)smem;               // [8][32][52] (aliases Ws)

    const int tid  = threadIdx.x;
    const int lane = tid & 31;
    const int w    = tid >> 5;
    const int gid  = lane >> 2;
    const int tig  = lane & 3;
    const int mg   = blockIdx.x >> 5;
    const int cg   = blockIdx.x & 31;
    const int rowbase = mg * 32;
    const int colbase = cg * 16;

    // Stage Whh slice as packed half2: local row lr = gate*16 + col, 256 words/row
    for (int i = tid; i < 48 * 128; i += 256) {     // 128 word-pairs per row
        int lr   = i >> 7;
        int cp   = (i & 127) * 2;                   // word index (pair of words)
        int grow = (lr >> 4) * 512 + colbase + (lr & 15);
        float4 v = *(const float4*)(Whh + (size_t)grow * 512 + cp * 2);
        Ws[lr * HS_PITCH + cp]     = pack_h2(v.x, v.y);
        Ws[lr * HS_PITCH + cp + 1] = pack_h2(v.z, v.w);
    }
    for (int i = tid; i < 32 * HS_PITCH; i += 256) Hs[i] = 0u;
    __syncthreads();

    // Pull W fragments: K slice = words [w*32, w*32+32), 4 chunks of 8 words
    const int kbw = w * 32;
    unsigned wf[4][6][2];
    #pragma unroll
    for (int kt = 0; kt < 4; kt++)
        #pragma unroll
        for (int nt = 0; nt < 6; nt++) {
            int base = (nt * 8 + gid) * HS_PITCH + kbw + kt * 8 + tig;
            wf[kt][nt][0] = Ws[base];
            wf[kt][nt][1] = Ws[base + 4];
        }
    __syncthreads();   // Ws free -> Sg

    const int bb = tid >> 3;
    const int jj = (tid * 2) & 15;               // even
    const float bn0 = __ldg(bn + colbase + jj);
    const float bn1 = __ldg(bn + colbase + jj + 1);
    float2 hp = make_float2(0.0f, 0.0f);

    float* Sgw = Sg + w * 32 * SG_PITCH;
    unsigned long long* myflag = &g_flag[(mg * 32 + cg) * 32];
    const unsigned long long* pf = &g_flag[(mg * 32 + w * 4 + (lane & 3)) * 32];

    // Restage addressing: 32 rows x 32 words slice; 8 uint4 per lane
    const int rs_rd = lane >> 3;                 // 0..3 row offset
    const int rs_w4 = (lane & 7) * 4;            // word offset in slice

    for (int t = 0; t < T_; t++) {
        const float* igb = g_ig + ((size_t)t * 128 + rowbase + bb) * 1536 + colbase + jj;
        float2 igr = __ldg((const float2*)(igb));
        float2 igz = __ldg((const float2*)(igb + 512));
        float2 ign = __ldg((const float2*)(igb + 1024));

        if (t > 0) {
            if (lane < 4) {
                while (ld_acquire(pf) < (unsigned long long)t) { }
            }
            __syncwarp();
            const unsigned* hsrc = g_h + (size_t)((t - 1) & 1) * HB2_;
            #pragma unroll
            for (int rr = 0; rr < 8; rr++) {
                int row = rr * 4 + rs_rd;
                const uint4* src = (const uint4*)(hsrc + (rowbase + row) * HW2_ + kbw + rs_w4);
                uint4 v;
                asm volatile("ld.global.cg.v4.u32 {%0,%1,%2,%3}, [%4];"
                             : "=r"(v.x), "=r"(v.y), "=r"(v.z), "=r"(v.w) : "l"(src));
                *(uint4*)&Hs[row * HS_PITCH + kbw + rs_w4] = v;
            }
        }

        float c[2][6][4];
        #pragma unroll
        for (int m = 0; m < 2; m++)
            #pragma unroll
            for (int n = 0; n < 6; n++)
                #pragma unroll
                for (int q = 0; q < 4; q++) c[m][n][q] = 0.0f;

        #pragma unroll
        for (int kt = 0; kt < 4; kt++) {
            const int kb = kbw + kt * 8;
            unsigned a[2][4];
            #pragma unroll
            for (int m = 0; m < 2; m++) {
                int r = m * 16 + gid;
                a[m][0] = Hs[r * HS_PITCH + kb + tig];
                a[m][1] = Hs[(r + 8) * HS_PITCH + kb + tig];
                a[m][2] = Hs[r * HS_PITCH + kb + tig + 4];
                a[m][3] = Hs[(r + 8) * HS_PITCH + kb + tig + 4];
            }
            #pragma unroll
            for (int n = 0; n < 6; n++) {
                mma16(c[0][n], a[0][0], a[0][1], a[0][2], a[0][3], wf[kt][n][0], wf[kt][n][1]);
                mma16(c[1][n], a[1][0], a[1][1], a[1][2], a[1][3], wf[kt][n][0], wf[kt][n][1]);
            }
        }

        #pragma unroll
        for (int m = 0; m < 2; m++) {
            int r0 = m * 16 + gid, r1 = r0 + 8;
            #pragma unroll
            for (int n = 0; n < 6; n++) {
                int cb = n * 8 + 2 * tig;
                *(float2*)&Sgw[r0 * SG_PITCH + cb] = make_float2(c[m][n][0], c[m][n][1]);
                *(float2*)&Sgw[r1 * SG_PITCH + cb] = make_float2(c[m][n][2], c[m][n][3]);
            }
        }
        __syncthreads();

        {
            float hr0 = 0.f, hr1 = 0.f, hz0 = 0.f, hz1 = 0.f, hn0 = 0.f, hn1 = 0.f;
            #pragma unroll
            for (int k = 0; k < 8; k++) {
                const float* s = Sg + k * 32 * SG_PITCH + bb * SG_PITCH;
                float2 vr = *(const float2*)(s + jj);
                float2 vz = *(const float2*)(s + 16 + jj);
                float2 vn = *(const float2*)(s + 32 + jj);
                hr0 += vr.x; hr1 += vr.y;
                hz0 += vz.x; hz1 += vz.y;
                hn0 += vn.x; hn1 += vn.y;
            }
            float r0 = sigf(igr.x + hr0);
            float r1 = sigf(igr.y + hr1);
            float z0 = sigf(igz.x + hz0);
            float z1 = sigf(igz.y + hz1);
            float n0 = tanhf_fast(ign.x + r0 * (hn0 + bn0));
            float n1 = tanhf_fast(ign.y + r1 * (hn1 + bn1));
            float h0 = (1.0f - z0) * n0 + z0 * hp.x;
            float h1 = (1.0f - z1) * n1 + z1 * hp.y;
            hp = make_float2(h0, h1);

            if (t < T_ - 1) {
                unsigned uv = pack_h2(h0, h1);
                unsigned* dst = g_h + (size_t)(t & 1) * HB2_
                                + (rowbase + bb) * HW2_ + (colbase + jj) / 2;
                asm volatile("st.global.cg.u32 [%0], %1;"
                             :: "l"(dst), "r"(uv) : "memory");
            } else {
                *(float2*)(g_hx + (rowbase + bb) * 512 + colbase + jj) =
                    make_float2(h0, h1);
            }
        }

        if (t == T_ - 1) break;
        __syncthreads();
        if (tid == 0) arrive_release(myflag);
    }
}

// ===========================================================================
// Kernel 3: out = h_final @ Wlin^T + blin (FROZEN)
// ===========================================================================
__global__ void __launch_bounds__(256) k_out(const float* __restrict__ Wlin,
                                             const float* __restrict__ blin,
                                             float* __restrict__ out) {
    const int wg   = blockIdx.x * 8 + (threadIdx.x >> 5);
    const int lane = threadIdx.x & 31;
    const int b    = wg >> 4;
    const int nb   = (wg & 15) * 32;

    float4 h4[4];
    #pragma unroll
    for (int q = 0; q < 4; q++)
        h4[q] = *(const float4*)(g_hx + b * 512 + q * 128 + lane * 4);

    #pragma unroll 4
    for (int i = 0; i < 32; i++) {
        int n = nb + i;
        const float* wr = Wlin + (size_t)n * 512;
        float s = 0.0f;
        #pragma unroll
        for (int q = 0; q < 4; q++) {
            float4 wv = __ldg((const float4*)(wr + q * 128 + lane * 4));
            s += h4[q].x * wv.x + h4[q].y * wv.y + h4[q].z * wv.z + h4[q].w * wv.w;
        }
        s += __shfl_xor_sync(0xFFFFFFFF, s, 16);
        s += __shfl_xor_sync(0xFFFFFFFF, s, 8);
        s += __shfl_xor_sync(0xFFFFFFFF, s, 4);
        s += __shfl_xor_sync(0xFFFFFFFF, s, 2);
        s += __shfl_xor_sync(0xFFFFFFFF, s, 1);
        if (lane == 0) {
            float v = s + __ldg(blin + n);
            if (n < L_) out[b * L_ + n] = v;
            else        out[(size_t)B_ * L_ + b * L_ + (n - L_)] = v;
        }
    }
}

// ===========================================================================
extern "C" void kernel_launch(void* const* d_in, const int* in_sizes, int n_in,
                              void* d_out, int out_size) {
    const float* x    = (const float*)d_in[0];
    const float* Wih  = (const float*)d_in[1];
    const float* Whh  = (const float*)d_in[2];
    const float* b    = (const float*)d_in[3];
    const float* bn   = (const float*)d_in[4];
    const float* Wlin = (const float*)d_in[5];
    const float* blin = (const float*)d_in[6];
    float* out = (float*)d_out;

    cudaFuncSetAttribute(k_rec, cudaFuncAttributeMaxDynamicSharedMemorySize,
                         SMEM_K2_BYTES);

    dim3 g1(12, 512);
    k_igemm<<<g1, 256>>>(x, Wih, b);
    k_zero<<<1, 256>>>();
    k_rec<<<128, 256, SMEM_K2_BYTES>>>(Whh, bn);
    k_out<<<256, 256>>>(Wlin, blin, out);
}

// round 17
// speedup vs baseline: 1.3808x; 1.0498x over previous
#include <cuda_runtime.h>
#include <cuda_fp16.h>

#define B_  128
#define T_  512
#define H_  512
#define L_  256
#define HW2_ 256                 // h row width in half2 words
#define HB2_ (B_ * HW2_)

__device__ unsigned g_ig[(size_t)T_ * B_ * 768];  // (T,B,3H) as half2 words
__device__ unsigned g_h[2 * HB2_];                // step-parity h (half2 words)
__device__ float    g_hx[B_ * H_];                // exact fp32 h_final
__device__ unsigned long long g_flag[128 * 32];   // 256B spacing

__device__ __forceinline__ unsigned pack_h2(float x, float y) {
    __half2 h = __floats2half2_rn(x, y);
    return *(unsigned*)&h;
}
__device__ __forceinline__ float2 unpack_h2(unsigned u) {
    return __half22float2(*(__half2*)&u);
}
__device__ __forceinline__ void mma16(float c[4],
                                      unsigned a0, unsigned a1, unsigned a2, unsigned a3,
                                      unsigned b0, unsigned b1) {
    asm volatile(
        "mma.sync.aligned.m16n8k16.row.col.f32.f16.f16.f32 "
        "{%0,%1,%2,%3}, {%4,%5,%6,%7}, {%8,%9}, {%0,%1,%2,%3};"
        : "+f"(c[0]), "+f"(c[1]), "+f"(c[2]), "+f"(c[3])
        : "r"(a0), "r"(a1), "r"(a2), "r"(a3), "r"(b0), "r"(b1));
}
__device__ __forceinline__ float sigf(float x) { return 1.0f / (1.0f + __expf(-x)); }
__device__ __forceinline__ float tanhf_fast(float x) {
    return 1.0f - __fdividef(2.0f, 1.0f + __expf(2.0f * x));
}
__device__ __forceinline__ unsigned long long arrive_release(unsigned long long* p) {
    unsigned long long old;
    asm volatile("atom.add.release.gpu.u64 %0, [%1], 1;" : "=l"(old) : "l"(p) : "memory");
    return old;
}
__device__ __forceinline__ unsigned long long ld_acquire(const unsigned long long* p) {
    unsigned long long v;
    asm volatile("ld.acquire.gpu.u64 %0, [%1];" : "=l"(v) : "l"(p) : "memory");
    return v;
}

__global__ void k_zero() {
    for (int i = threadIdx.x; i < 128 * 32; i += 256) g_flag[i] = 0ULL;
}

// ===========================================================================
// Kernel 1 (fp16 HMMA + reg-prefetch pipeline): IG = X@Wih^T + b  -> half2
//   Tile 128x128, grid (12,512), 256 thr. Chunk c+1's LDGs issued under
//   chunk c's MMA (register double-buffer; no extra SMEM).
// ===========================================================================
__global__ void __launch_bounds__(256) k_igemm(const float* __restrict__ x,
                                               const float* __restrict__ Wih,
                                               const float* __restrict__ bias) {
    __shared__ unsigned As[128][12];
    __shared__ unsigned Bs[128][12];

    const int t   = blockIdx.y;
    const int n0  = blockIdx.x * 128;
    const int tid = threadIdx.x;
    const int w    = tid >> 5;
    const int lane = tid & 31;
    const int gid  = lane >> 2;
    const int tig  = lane & 3;
    const int mrow = (w >> 2) * 64;
    const int ncol = (w & 3) * 32;

    const int lr = tid >> 2;       // rows lr and lr+64
    const int lc = tid & 3;        // float4 index within 16-col chunk

    float acc[4][4][4];
    #pragma unroll
    for (int i = 0; i < 4; i++)
        #pragma unroll
        for (int j = 0; j < 4; j++)
            #pragma unroll
            for (int q = 0; q < 4; q++) acc[i][j][q] = 0.0f;

    float4 va[2], vb[2];
    // preload chunk 0
    #pragma unroll
    for (int it = 0; it < 2; it++) {
        int r = lr + it * 64;
        va[it] = *(const float4*)(x + ((size_t)r * 512 + t) * 512 + lc * 4);
        vb[it] = *(const float4*)(Wih + (size_t)(n0 + r) * 512 + lc * 4);
    }

    for (int c = 0; c < 32; c++) {
        // Store current regs to SMEM (packed half2)
        #pragma unroll
        for (int it = 0; it < 2; it++) {
            int r = lr + it * 64;
            As[r][2 * lc]     = pack_h2(va[it].x, va[it].y);
            As[r][2 * lc + 1] = pack_h2(va[it].z, va[it].w);
            Bs[r][2 * lc]     = pack_h2(vb[it].x, vb[it].y);
            Bs[r][2 * lc + 1] = pack_h2(vb[it].z, vb[it].w);
        }
        __syncthreads();

        // Prefetch next chunk under this chunk's MMA
        if (c < 31) {
            int k0 = (c + 1) * 16;
            #pragma unroll
            for (int it = 0; it < 2; it++) {
                int r = lr + it * 64;
                va[it] = *(const float4*)(x + ((size_t)r * 512 + t) * 512 + k0 + lc * 4);
                vb[it] = *(const float4*)(Wih + (size_t)(n0 + r) * 512 + k0 + lc * 4);
            }
        }

        unsigned a[4][4];
        #pragma unroll
        for (int mt = 0; mt < 4; mt++) {
            int r = mrow + mt * 16 + gid;
            a[mt][0] = As[r][tig];
            a[mt][1] = As[r + 8][tig];
            a[mt][2] = As[r][tig + 4];
            a[mt][3] = As[r + 8][tig + 4];
        }
        #pragma unroll
        for (int nt = 0; nt < 4; nt++) {
            int n = ncol + nt * 8 + gid;
            unsigned b0 = Bs[n][tig];
            unsigned b1 = Bs[n][tig + 4];
            #pragma unroll
            for (int mt = 0; mt < 4; mt++)
                mma16(acc[mt][nt], a[mt][0], a[mt][1], a[mt][2], a[mt][3], b0, b1);
        }
        __syncthreads();
    }

    // Epilogue: half2 words into g_ig
    #pragma unroll
    for (int mt = 0; mt < 4; mt++) {
        #pragma unroll
        for (int nt = 0; nt < 4; nt++) {
            int r0 = mrow + mt * 16 + gid;
            int c0 = n0 + ncol + nt * 8 + 2 * tig;   // even
            float bv0 = __ldg(bias + c0);
            float bv1 = __ldg(bias + c0 + 1);
            g_ig[((size_t)t * 128 + r0) * 768 + (c0 >> 1)] =
                pack_h2(acc[mt][nt][0] + bv0, acc[mt][nt][1] + bv1);
            g_ig[((size_t)t * 128 + r0 + 8) * 768 + (c0 >> 1)] =
                pack_h2(acc[mt][nt][2] + bv0, acc[mt][nt][3] + bv1);
        }
    }
}

// ===========================================================================
// Kernel 2 (fp16 MMA): persistent GRU recurrence (R16 structure; ig half2)
// ===========================================================================
#define HS_PITCH 260
#define SG_PITCH 52
#define SG_WORDS (8 * 32 * SG_PITCH)
#define K2_HS_OFF SG_WORDS
#define SMEM_K2_BYTES ((SG_WORDS + 32 * HS_PITCH) * 4)

__global__ void __launch_bounds__(256, 1) k_rec(const float* __restrict__ Whh,
                                                const float* __restrict__ bn) {
    extern __shared__ unsigned smem[];
    unsigned* Ws = smem;
    unsigned* Hs = smem + K2_HS_OFF;
    float*    Sg = (float*)smem;

    const int tid  = threadIdx.x;
    const int lane = tid & 31;
    const int w    = tid >> 5;
    const int gid  = lane >> 2;
    const int tig  = lane & 3;
    const int mg   = blockIdx.x >> 5;
    const int cg   = blockIdx.x & 31;
    const int rowbase = mg * 32;
    const int colbase = cg * 16;

    for (int i = tid; i < 48 * 128; i += 256) {
        int lr   = i >> 7;
        int cp   = (i & 127) * 2;
        int grow = (lr >> 4) * 512 + colbase + (lr & 15);
        float4 v = *(const float4*)(Whh + (size_t)grow * 512 + cp * 2);
        Ws[lr * HS_PITCH + cp]     = pack_h2(v.x, v.y);
        Ws[lr * HS_PITCH + cp + 1] = pack_h2(v.z, v.w);
    }
    for (int i = tid; i < 32 * HS_PITCH; i += 256) Hs[i] = 0u;
    __syncthreads();

    const int kbw = w * 32;
    unsigned wf[4][6][2];
    #pragma unroll
    for (int kt = 0; kt < 4; kt++)
        #pragma unroll
        for (int nt = 0; nt < 6; nt++) {
            int base = (nt * 8 + gid) * HS_PITCH + kbw + kt * 8 + tig;
            wf[kt][nt][0] = Ws[base];
            wf[kt][nt][1] = Ws[base + 4];
        }
    __syncthreads();

    const int bb = tid >> 3;
    const int jj = (tid * 2) & 15;
    const float bn0 = __ldg(bn + colbase + jj);
    const float bn1 = __ldg(bn + colbase + jj + 1);
    float2 hp = make_float2(0.0f, 0.0f);

    float* Sgw = Sg + w * 32 * SG_PITCH;
    unsigned long long* myflag = &g_flag[(mg * 32 + cg) * 32];
    const unsigned long long* pf = &g_flag[(mg * 32 + w * 4 + (lane & 3)) * 32];

    const int rs_rd = lane >> 3;
    const int rs_w4 = (lane & 7) * 4;

    for (int t = 0; t < T_; t++) {
        const unsigned* igb = g_ig + ((size_t)t * 128 + rowbase + bb) * 768
                              + ((colbase + jj) >> 1);
        unsigned uigr = __ldg(igb);
        unsigned uigz = __ldg(igb + 256);
        unsigned uign = __ldg(igb + 512);

        if (t > 0) {
            if (lane < 4) {
                while (ld_acquire(pf) < (unsigned long long)t) { }
            }
            __syncwarp();
            const unsigned* hsrc = g_h + (size_t)((t - 1) & 1) * HB2_;
            #pragma unroll
            for (int rr = 0; rr < 8; rr++) {
                int row = rr * 4 + rs_rd;
                const uint4* src = (const uint4*)(hsrc + (rowbase + row) * HW2_ + kbw + rs_w4);
                uint4 v;
                asm volatile("ld.global.cg.v4.u32 {%0,%1,%2,%3}, [%4];"
                             : "=r"(v.x), "=r"(v.y), "=r"(v.z), "=r"(v.w) : "l"(src));
                *(uint4*)&Hs[row * HS_PITCH + kbw + rs_w4] = v;
            }
        }

        float c[2][6][4];
        #pragma unroll
        for (int m = 0; m < 2; m++)
            #pragma unroll
            for (int n = 0; n < 6; n++)
                #pragma unroll
                for (int q = 0; q < 4; q++) c[m][n][q] = 0.0f;

        #pragma unroll
        for (int kt = 0; kt < 4; kt++) {
            const int kb = kbw + kt * 8;
            unsigned a[2][4];
            #pragma unroll
            for (int m = 0; m < 2; m++) {
                int r = m * 16 + gid;
                a[m][0] = Hs[r * HS_PITCH + kb + tig];
                a[m][1] = Hs[(r + 8) * HS_PITCH + kb + tig];
                a[m][2] = Hs[r * HS_PITCH + kb + tig + 4];
                a[m][3] = Hs[(r + 8) * HS_PITCH + kb + tig + 4];
            }
            #pragma unroll
            for (int n = 0; n < 6; n++) {
                mma16(c[0][n], a[0][0], a[0][1], a[0][2], a[0][3], wf[kt][n][0], wf[kt][n][1]);
                mma16(c[1][n], a[1][0], a[1][1], a[1][2], a[1][3], wf[kt][n][0], wf[kt][n][1]);
            }
        }

        #pragma unroll
        for (int m = 0; m < 2; m++) {
            int r0 = m * 16 + gid, r1 = r0 + 8;
            #pragma unroll
            for (int n = 0; n < 6; n++) {
                int cb = n * 8 + 2 * tig;
                *(float2*)&Sgw[r0 * SG_PITCH + cb] = make_float2(c[m][n][0], c[m][n][1]);
                *(float2*)&Sgw[r1 * SG_PITCH + cb] = make_float2(c[m][n][2], c[m][n][3]);
            }
        }
        __syncthreads();

        {
            float hr0 = 0.f, hr1 = 0.f, hz0 = 0.f, hz1 = 0.f, hn0 = 0.f, hn1 = 0.f;
            #pragma unroll
            for (int k = 0; k < 8; k++) {
                const float* s = Sg + k * 32 * SG_PITCH + bb * SG_PITCH;
                float2 vr = *(const float2*)(s + jj);
                float2 vz = *(const float2*)(s + 16 + jj);
                float2 vn = *(const float2*)(s + 32 + jj);
                hr0 += vr.x; hr1 += vr.y;
                hz0 += vz.x; hz1 += vz.y;
                hn0 += vn.x; hn1 += vn.y;
            }
            float2 igr = unpack_h2(uigr);
            float2 igz = unpack_h2(uigz);
            float2 ign = unpack_h2(uign);
            float r0 = sigf(igr.x + hr0);
            float r1 = sigf(igr.y + hr1);
            float z0 = sigf(igz.x + hz0);
            float z1 = sigf(igz.y + hz1);
            float n0 = tanhf_fast(ign.x + r0 * (hn0 + bn0));
            float n1 = tanhf_fast(ign.y + r1 * (hn1 + bn1));
            float h0 = (1.0f - z0) * n0 + z0 * hp.x;
            float h1 = (1.0f - z1) * n1 + z1 * hp.y;
            hp = make_float2(h0, h1);

            if (t < T_ - 1) {
                unsigned uv = pack_h2(h0, h1);
                unsigned* dst = g_h + (size_t)(t & 1) * HB2_
                                + (rowbase + bb) * HW2_ + ((colbase + jj) >> 1);
                asm volatile("st.global.cg.u32 [%0], %1;"
                             :: "l"(dst), "r"(uv) : "memory");
            } else {
                *(float2*)(g_hx + (rowbase + bb) * 512 + colbase + jj) =
                    make_float2(h0, h1);
            }
        }

        if (t == T_ - 1) break;
        __syncthreads();
        if (tid == 0) arrive_release(myflag);
    }
}

// ===========================================================================
// Kernel 3: out = h_final @ Wlin^T + blin (FROZEN)
// ===========================================================================
__global__ void __launch_bounds__(256) k_out(const float* __restrict__ Wlin,
                                             const float* __restrict__ blin,
                                             float* __restrict__ out) {
    const int wg   = blockIdx.x * 8 + (threadIdx.x >> 5);
    const int lane = threadIdx.x & 31;
    const int b    = wg >> 4;
    const int nb   = (wg & 15) * 32;

    float4 h4[4];
    #pragma unroll
    for (int q = 0; q < 4; q++)
        h4[q] = *(const float4*)(g_hx + b * 512 + q * 128 + lane * 4);

    #pragma unroll 4
    for (int i = 0; i < 32; i++) {
        int n = nb + i;
        const float* wr = Wlin + (size_t)n * 512;
        float s = 0.0f;
        #pragma unroll
        for (int q = 0; q < 4; q++) {
            float4 wv = __ldg((const float4*)(wr + q * 128 + lane * 4));
            s += h4[q].x * wv.x + h4[q].y * wv.y + h4[q].z * wv.z + h4[q].w * wv.w;
        }
        s += __shfl_xor_sync(0xFFFFFFFF, s, 16);
        s += __shfl_xor_sync(0xFFFFFFFF, s, 8);
        s += __shfl_xor_sync(0xFFFFFFFF, s, 4);
        s += __shfl_xor_sync(0xFFFFFFFF, s, 2);
        s += __shfl_xor_sync(0xFFFFFFFF, s, 1);
        if (lane == 0) {
            float v = s + __ldg(blin + n);
            if (n < L_) out[b * L_ + n] = v;
            else        out[(size_t)B_ * L_ + b * L_ + (n - L_)] = v;
        }
    }
}

// ===========================================================================
extern "C" void kernel_launch(void* const* d_in, const int* in_sizes, int n_in,
                              void* d_out, int out_size) {
    const float* x    = (const float*)d_in[0];
    const float* Wih  = (const float*)d_in[1];
    const float* Whh  = (const float*)d_in[2];
    const float* b    = (const float*)d_in[3];
    const float* bn   = (const float*)d_in[4];
    const float* Wlin = (const float*)d_in[5];
    const float* blin = (const float*)d_in[6];
    float* out = (float*)d_out;

    cudaFuncSetAttribute(k_rec, cudaFuncAttributeMaxDynamicSharedMemorySize,
                         SMEM_K2_BYTES);

    dim3 g1(12, 512);
    k_igemm<<<g1, 256>>>(x, Wih, b);
    k_zero<<<1, 256>>>();
    k_rec<<<128, 256, SMEM_K2_BYTES>>>(Whh, bn);
    k_out<<<256, 256>>>(Wlin, blin, out);
}